// round 8
// baseline (speedup 1.0000x reference)
#include <cuda_runtime.h>

// Problem constants
#define HH 192
#define WW 192
#define HW (192*192)
#define BB 4
#define DD 8
#define NF 32
#define NFH 40
#define CGATE 56
#define EPS 1e-5f
#define NPART 288   // BB * 12 * 6 BN partial blocks

// ---------------- scratch (device globals; no allocation) ----------------
__device__ float g_hs[BB*8*HW];
__device__ float g_cs[BB*8*HW];
__device__ float g_fic[BB*24*HW];      // raw f,i,c gate conv outputs
__device__ float g_r[BB*NFH*HW];       // [cs(8), sigmoid(q)(32)]
__device__ float g_y0[BB*NFH*HW];      // conv0 raw output (pre-BN)
__device__ float g_y1[BB*NFH*HW];      // conv1 raw output (pre-BN)
__device__ float g_wgate[CGATE*NFH*9];
__device__ float g_bgate[CGATE];
__device__ float g_wtailT[NFH*25*12];  // [ci][tap][co(12, pad)] transposed tail weights
__device__ float g_btail[11];
__device__ float g_partS[NFH*NPART];
__device__ float g_partQ[NFH*NPART];
__device__ float g_bna[2][NFH];        // BN fused scale
__device__ float g_bnb[2][NFH];        // BN fused shift

// ---------------- helpers ----------------
__device__ __forceinline__ float sigm(float x) { return 1.f / (1.f + expf(-x)); }

__device__ __forceinline__ unsigned long long pack2(float x) {
    unsigned long long r;
    asm("mov.b64 %0, {%1, %1};" : "=l"(r) : "r"(__float_as_uint(x)));
    return r;
}
__device__ __forceinline__ void fma2(unsigned long long& a, unsigned long long x, unsigned long long w) {
    asm("fma.rn.f32x2 %0, %1, %2, %0;" : "+l"(a) : "l"(x), "l"(w));
}
__device__ __forceinline__ float2 unpack2(unsigned long long v) {
    unsigned int lo, hi;
    asm("mov.b64 {%0, %1}, %2;" : "=r"(lo), "=r"(hi) : "l"(v));
    return make_float2(__uint_as_float(lo), __uint_as_float(hi));
}

// ---------------- init / prep ----------------
__global__ void zero_state() {
    int i = blockIdx.x * blockDim.x + threadIdx.x;
    if (i < BB*8*HW) { g_hs[i] = 0.f; g_cs[i] = 0.f; }
}

__global__ void prep_gate(const float* __restrict__ Wf, const float* __restrict__ bf,
                          const float* __restrict__ Wi, const float* __restrict__ bi,
                          const float* __restrict__ Wc, const float* __restrict__ bc,
                          const float* __restrict__ Wq, const float* __restrict__ bq) {
    int i = blockIdx.x * blockDim.x + threadIdx.x;
    const int WSZ = NFH * 9;
    if (i < CGATE * WSZ) {
        int o = i / WSZ, r = i % WSZ;
        float v;
        if (o < 8)       v = Wf[o * WSZ + r];
        else if (o < 16) v = Wi[(o - 8) * WSZ + r];
        else if (o < 24) v = Wc[(o - 16) * WSZ + r];
        else             v = Wq[(o - 24) * WSZ + r];
        g_wgate[i] = v;
    }
    if (i < CGATE) {
        float bv = (i < 8) ? bf[i] : (i < 16) ? bi[i - 8] : (i < 24) ? bc[i - 16] : bq[i - 24];
        g_bgate[i] = bv;
    }
}

__global__ void prep_tail(const float* __restrict__ W2, const float* __restrict__ b2w,
                          const float* __restrict__ Wh, const float* __restrict__ bh) {
    int i = blockIdx.x * blockDim.x + threadIdx.x;
    if (i < NFH * 25 * 12) {
        int o = i % 12;
        int rt = i / 12;            // ci*25 + tap
        int ci = rt / 25, k = rt % 25, ky = k / 5, kx = k % 5;
        float v = 0.f;
        if (o < 3) {
            v = W2[(o * NFH + ci) * 25 + k];
        } else if (o < 11) {
            int oo = o - 3;
            if (ky >= 1 && ky <= 3 && kx >= 1 && kx <= 3)
                v = Wh[(oo * NFH + ci) * 9 + (ky - 1) * 3 + (kx - 1)];
        }
        g_wtailT[i] = v;
    }
    if (i < 11) g_btail[i] = (i < 3) ? b2w[i] : bh[i - 3];
}

// ---------------- gate conv (3x3, 40 -> 56), f32x2, 32x16 tile, 4px x 8co/thread --------
__global__ __launch_bounds__(128, 6) void gates_kernel(const float* __restrict__ xin, int t) {
    __shared__ float swT[NFH * 9 * 8];    // [ci][k][co] 2880 f = 11.5KB
    __shared__ float st[2][18][36];       // ping-pong, 34 cols used, 5.2KB
    int n = blockIdx.z / 7, grp = blockIdx.z % 7;
    int tx = threadIdx.x, ty = threadIdx.y;
    int tid = ty * 8 + tx;
    for (int i = tid; i < 8 * NFH * 9; i += 128) {
        int o = i / (NFH * 9), r = i % (NFH * 9);
        swT[r * 8 + o] = g_wgate[(grp * 8) * (NFH * 9) + i];
    }
    unsigned long long acc[4][4];
    #pragma unroll
    for (int p = 0; p < 4; p++) { acc[p][0]=acc[p][1]=acc[p][2]=acc[p][3]=0ull; }
    int y0 = blockIdx.y * 16, x0 = blockIdx.x * 32;

    auto loadci = [&](int ci, int buf) {
        const float* src = (ci < NF)
            ? (xin + ((size_t)(n * DD + t) * NF + ci) * HW)
            : (g_hs + ((size_t)n * 8 + (ci - NF)) * HW);
        for (int i = tid; i < 18 * 34; i += 128) {
            int r = i / 34, c = i % 34;
            int yy = y0 - 1 + r, xx = x0 - 1 + c;
            st[buf][r][c] = (yy >= 0 && yy < HH && xx >= 0 && xx < WW) ? src[yy * WW + xx] : 0.f;
        }
    };

    loadci(0, 0);
    __syncthreads();
    for (int ci = 0; ci < NFH; ci++) {
        if (ci + 1 < NFH) loadci(ci + 1, (ci + 1) & 1);
        int buf = ci & 1;
        #pragma unroll
        for (int ky = 0; ky < 3; ky++) {
            const float* row = &st[buf][ty + ky][tx * 4];
            float4 t0 = *(const float4*)row;
            float t4 = row[4], t5 = row[5];
            unsigned long long xx[6];
            xx[0]=pack2(t0.x); xx[1]=pack2(t0.y); xx[2]=pack2(t0.z); xx[3]=pack2(t0.w);
            xx[4]=pack2(t4);   xx[5]=pack2(t5);
            #pragma unroll
            for (int kx = 0; kx < 3; kx++) {
                const ulonglong2* wp = (const ulonglong2*)&swT[(ci * 9 + ky * 3 + kx) * 8];
                ulonglong2 wA = wp[0], wB = wp[1];
                #pragma unroll
                for (int p = 0; p < 4; p++) {
                    unsigned long long xv = xx[p + kx];
                    fma2(acc[p][0], xv, wA.x);
                    fma2(acc[p][1], xv, wA.y);
                    fma2(acc[p][2], xv, wB.x);
                    fma2(acc[p][3], xv, wB.y);
                }
            }
        }
        __syncthreads();
    }
    float v[4][8];
    #pragma unroll
    for (int p = 0; p < 4; p++) {
        #pragma unroll
        for (int j = 0; j < 4; j++) {
            float2 u = unpack2(acc[p][j]);
            v[p][2*j] = u.x; v[p][2*j+1] = u.y;
        }
    }
    int yy = y0 + ty, xb = x0 + tx * 4;
    #pragma unroll
    for (int co = 0; co < 8; co++) {
        int oc = grp * 8 + co;
        float b = g_bgate[oc];
        float4 A;
        A.x=v[0][co]+b; A.y=v[1][co]+b; A.z=v[2][co]+b; A.w=v[3][co]+b;
        if (oc < 24) {
            *(float4*)&g_fic[((size_t)n * 24 + oc) * HW + yy * WW + xb] = A;
        } else {
            A.x=sigm(A.x); A.y=sigm(A.y); A.z=sigm(A.z); A.w=sigm(A.w);
            *(float4*)&g_r[((size_t)n * NFH + 8 + (oc - 24)) * HW + yy * WW + xb] = A;
        }
    }
}

// ---------------- LSTM cell state update ----------------
__global__ void cs_update() {
    int i = blockIdx.x * 256 + threadIdx.x;
    if (i >= BB * 8 * HW) return;
    int n = i / (8 * HW);
    int r = i % (8 * HW);
    int c = r / HW, p = r % HW;
    size_t base = (size_t)n * 24 * HW + p;
    float zf = g_fic[base + (size_t)c * HW];
    float zi = g_fic[base + (size_t)(8 + c) * HW];
    float zc = g_fic[base + (size_t)(16 + c) * HW];
    float cs = sigm(zf) * g_cs[i] + sigm(zi) * tanhf(zc);
    g_cs[i] = cs;
    g_r[((size_t)n * NFH + c) * HW + p] = cs;
}

// ---------------- 5x5 conv 40->40, f32x2, 32x16 tile, 4px x 8co/thread + BN partials ----
template <int PHASE>
__global__ __launch_bounds__(128, 5) void conv5_kernel(const float* __restrict__ Wt) {
    __shared__ float swT[NFH * 25 * 8];   // [ci][k][co] 8000 f = 32KB
    __shared__ float st[2][20][40];       // ping-pong, 36 cols used, 6.4KB
    __shared__ float red[2][4][8];
    int n = blockIdx.z / 5, cog = blockIdx.z % 5;
    int tx = threadIdx.x, ty = threadIdx.y;
    int tid = ty * 8 + tx;
    for (int i = tid; i < 8 * NFH * 25; i += 128) {
        int o = i / (NFH * 25), r = i % (NFH * 25);
        swT[r * 8 + o] = Wt[(cog * 8) * (NFH * 25) + i];
    }
    unsigned long long acc[4][4];
    #pragma unroll
    for (int p = 0; p < 4; p++) { acc[p][0]=acc[p][1]=acc[p][2]=acc[p][3]=0ull; }
    int y0 = blockIdx.y * 16, x0 = blockIdx.x * 32;

    auto loadci = [&](int ci, int buf) {
        const float* src = (PHASE ? g_y0 : g_r) + ((size_t)n * NFH + ci) * HW;
        float a = 0.f, b = 0.f;
        if (PHASE) { a = g_bna[0][ci]; b = g_bnb[0][ci]; }
        for (int i = tid; i < 20 * 36; i += 128) {
            int r = i / 36, c = i % 36;
            int yy = y0 - 2 + r, xx = x0 - 2 + c;
            float v = 0.f;
            if (yy >= 0 && yy < HH && xx >= 0 && xx < WW) {
                v = src[yy * WW + xx];
                if (PHASE) v = fmaxf(0.f, fmaf(v, a, b));
            }
            st[buf][r][c] = v;
        }
    };

    loadci(0, 0);
    __syncthreads();
    for (int ci = 0; ci < NFH; ci++) {
        if (ci + 1 < NFH) loadci(ci + 1, (ci + 1) & 1);
        int buf = ci & 1;
        #pragma unroll
        for (int ky = 0; ky < 5; ky++) {
            const float* row = &st[buf][ty + ky][tx * 4];
            float4 t0 = *(const float4*)row;
            float4 t1 = *(const float4*)(row + 4);
            unsigned long long xx[8];
            xx[0]=pack2(t0.x); xx[1]=pack2(t0.y); xx[2]=pack2(t0.z); xx[3]=pack2(t0.w);
            xx[4]=pack2(t1.x); xx[5]=pack2(t1.y); xx[6]=pack2(t1.z); xx[7]=pack2(t1.w);
            #pragma unroll
            for (int kx = 0; kx < 5; kx++) {
                const ulonglong2* wp = (const ulonglong2*)&swT[(ci * 25 + ky * 5 + kx) * 8];
                ulonglong2 wA = wp[0], wB = wp[1];
                #pragma unroll
                for (int p = 0; p < 4; p++) {
                    unsigned long long xv = xx[p + kx];
                    fma2(acc[p][0], xv, wA.x);
                    fma2(acc[p][1], xv, wA.y);
                    fma2(acc[p][2], xv, wB.x);
                    fma2(acc[p][3], xv, wB.y);
                }
            }
        }
        __syncthreads();
    }
    float v[4][8];
    #pragma unroll
    for (int p = 0; p < 4; p++) {
        #pragma unroll
        for (int j = 0; j < 4; j++) {
            float2 u = unpack2(acc[p][j]);
            v[p][2*j] = u.x; v[p][2*j+1] = u.y;
        }
    }
    float* outp = PHASE ? g_y1 : g_y0;
    int yy = y0 + ty, xb = x0 + tx * 4;
    float s[8], q[8];
    #pragma unroll
    for (int co = 0; co < 8; co++) {
        float4 A;
        A.x=v[0][co]; A.y=v[1][co]; A.z=v[2][co]; A.w=v[3][co];
        *(float4*)&outp[((size_t)n * NFH + cog * 8 + co) * HW + yy * WW + xb] = A;
        s[co] = A.x + A.y + A.z + A.w;
        q[co] = A.x*A.x + A.y*A.y + A.z*A.z + A.w*A.w;
    }
    int lane = tid & 31, warp = tid >> 5;
    #pragma unroll
    for (int off = 16; off; off >>= 1) {
        #pragma unroll
        for (int co = 0; co < 8; co++) {
            s[co] += __shfl_down_sync(0xffffffffu, s[co], off);
            q[co] += __shfl_down_sync(0xffffffffu, q[co], off);
        }
    }
    if (lane == 0) {
        #pragma unroll
        for (int co = 0; co < 8; co++) { red[0][warp][co] = s[co]; red[1][warp][co] = q[co]; }
    }
    __syncthreads();
    if (tid < 8) {
        float S = red[0][0][tid] + red[0][1][tid] + red[0][2][tid] + red[0][3][tid];
        float Q = red[1][0][tid] + red[1][1][tid] + red[1][2][tid] + red[1][3][tid];
        int ch = cog * 8 + tid;
        int bxy = (n * 12 + blockIdx.y) * 6 + blockIdx.x;
        g_partS[ch * NPART + bxy] = S;
        g_partQ[ch * NPART + bxy] = Q;
    }
}

// ---------------- BN statistics finalize ----------------
__global__ void bn_reduce(int phase, const float* __restrict__ gamma, const float* __restrict__ beta) {
    int ch = blockIdx.x;
    int tid = threadIdx.x;
    __shared__ float ss[128], sq[128];
    float s = 0.f, q = 0.f;
    for (int i = tid; i < NPART; i += 128) { s += g_partS[ch * NPART + i]; q += g_partQ[ch * NPART + i]; }
    ss[tid] = s; sq[tid] = q;
    __syncthreads();
    for (int off = 64; off; off >>= 1) {
        if (tid < off) { ss[tid] += ss[tid + off]; sq[tid] += sq[tid + off]; }
        __syncthreads();
    }
    if (tid == 0) {
        const float N = (float)(BB * HW);
        float mean = ss[0] / N;
        float var = sq[0] / N - mean * mean;
        float inv = rsqrtf(var + EPS);
        float a = gamma[ch] * inv;
        g_bna[phase][ch] = a;
        g_bnb[phase][ch] = beta[ch] - mean * a;
    }
}

// ---------------- tail: combined 5x5 conv, 40 -> 12(pad), f32x2, 32x16 tile ------------
__global__ __launch_bounds__(128, 4) void tail_kernel(float* __restrict__ outp, int t) {
    __shared__ float st[2][20][40];   // 36 cols used
    int n = blockIdx.z;
    int tx = threadIdx.x, ty = threadIdx.y;
    int tid = ty * 8 + tx;
    unsigned long long acc[4][6];
    #pragma unroll
    for (int p = 0; p < 4; p++)
        #pragma unroll
        for (int j = 0; j < 6; j++) acc[p][j] = 0ull;
    int y0 = blockIdx.y * 16, x0 = blockIdx.x * 32;

    auto loadci = [&](int ci, int buf) {
        const float* src = g_y1 + ((size_t)n * NFH + ci) * HW;
        float a = g_bna[1][ci], b = g_bnb[1][ci];
        for (int i = tid; i < 20 * 36; i += 128) {
            int r = i / 36, c = i % 36;
            int yy = y0 - 2 + r, xx = x0 - 2 + c;
            float v = 0.f;
            if (yy >= 0 && yy < HH && xx >= 0 && xx < WW)
                v = fmaxf(0.f, fmaf(src[yy * WW + xx], a, b));
            st[buf][r][c] = v;
        }
    };

    loadci(0, 0);
    __syncthreads();
    for (int ci = 0; ci < NFH; ci++) {
        if (ci + 1 < NFH) loadci(ci + 1, (ci + 1) & 1);
        int buf = ci & 1;
        #pragma unroll
        for (int ky = 0; ky < 5; ky++) {
            const float* row = &st[buf][ty + ky][tx * 4];
            float4 t0 = *(const float4*)row;
            float4 t1 = *(const float4*)(row + 4);
            unsigned long long xx[8];
            xx[0]=pack2(t0.x); xx[1]=pack2(t0.y); xx[2]=pack2(t0.z); xx[3]=pack2(t0.w);
            xx[4]=pack2(t1.x); xx[5]=pack2(t1.y); xx[6]=pack2(t1.z); xx[7]=pack2(t1.w);
            #pragma unroll
            for (int kx = 0; kx < 5; kx++) {
                const ulonglong2* wp =
                    (const ulonglong2*)&g_wtailT[(ci * 25 + ky * 5 + kx) * 12];
                ulonglong2 wA = __ldg(wp), wB = __ldg(wp + 1), wC = __ldg(wp + 2);
                #pragma unroll
                for (int p = 0; p < 4; p++) {
                    unsigned long long xv = xx[p + kx];
                    fma2(acc[p][0], xv, wA.x);
                    fma2(acc[p][1], xv, wA.y);
                    fma2(acc[p][2], xv, wB.x);
                    fma2(acc[p][3], xv, wB.y);
                    fma2(acc[p][4], xv, wC.x);
                    fma2(acc[p][5], xv, wC.y);
                }
            }
        }
        __syncthreads();
    }
    float v[4][12];
    #pragma unroll
    for (int p = 0; p < 4; p++) {
        #pragma unroll
        for (int j = 0; j < 6; j++) {
            float2 u = unpack2(acc[p][j]);
            v[p][2*j] = u.x; v[p][2*j+1] = u.y;
        }
    }
    int yy = y0 + ty, xb = x0 + tx * 4;
    #pragma unroll
    for (int co = 0; co < 11; co++) {
        float b = g_btail[co];
        float4 o; o.x=v[0][co]+b; o.y=v[1][co]+b; o.z=v[2][co]+b; o.w=v[3][co]+b;
        if (co < 3) {
            *(float4*)&outp[(((size_t)n * 3 + co) * DD + t) * HW + yy * WW + xb] = o;
        } else {
            *(float4*)&g_hs[((size_t)n * 8 + (co - 3)) * HW + yy * WW + xb] = o;
        }
    }
}

// ---------------- launcher ----------------
extern "C" void kernel_launch(void* const* d_in, const int* in_sizes, int n_in,
                              void* d_out, int out_size) {
    const float* x1  = (const float*)d_in[0];
    const float* x2  = (const float*)d_in[1];
    const float* Wf  = (const float*)d_in[2];
    const float* bf  = (const float*)d_in[3];
    const float* Wi  = (const float*)d_in[4];
    const float* bi  = (const float*)d_in[5];
    const float* Wc  = (const float*)d_in[6];
    const float* bc  = (const float*)d_in[7];
    const float* Wq  = (const float*)d_in[8];
    const float* bq  = (const float*)d_in[9];
    const float* W0  = (const float*)d_in[10];
    const float* g0  = (const float*)d_in[11];
    const float* be0 = (const float*)d_in[12];
    const float* W1  = (const float*)d_in[13];
    const float* g1  = (const float*)d_in[14];
    const float* be1 = (const float*)d_in[15];
    const float* W2  = (const float*)d_in[16];
    const float* b2w = (const float*)d_in[17];
    const float* Wh  = (const float*)d_in[18];
    const float* bh  = (const float*)d_in[19];
    float* out = (float*)d_out;

    dim3 cb(8, 16, 1);
    dim3 gGate(6, 12, BB * 7);
    dim3 gConv(6, 12, BB * 5);
    dim3 gTail(6, 12, BB);

    zero_state<<<(BB*8*HW + 255) / 256, 256>>>();
    prep_gate<<<(CGATE*NFH*9 + 255) / 256, 256>>>(Wf, bf, Wi, bi, Wc, bc, Wq, bq);
    prep_tail<<<(NFH*25*12 + 255) / 256, 256>>>(W2, b2w, Wh, bh);

    const size_t OUT_HALF = (size_t)BB * 3 * DD * HW;
    for (int t = 0; t < DD; t++) {
        for (int cell = 0; cell < 2; cell++) {
            gates_kernel<<<gGate, cb>>>(cell ? x2 : x1, t);
            cs_update<<<(BB*8*HW + 255) / 256, 256>>>();
            conv5_kernel<0><<<gConv, cb>>>(W0);
            bn_reduce<<<NFH, 128>>>(0, g0, be0);
            conv5_kernel<1><<<gConv, cb>>>(W1);
            bn_reduce<<<NFH, 128>>>(1, g1, be1);
            tail_kernel<<<gTail, cb>>>(out + (size_t)cell * OUT_HALF, t);
        }
    }
}

// round 9
// speedup vs baseline: 2.1325x; 2.1325x over previous
#include <cuda_runtime.h>
#include <cstdint>

// Problem constants
#define HH 192
#define WW 192
#define HW (192*192)
#define BB 4
#define DD 8
#define NF 32
#define NFH 40
#define EPS 1e-5f
#define NPART 2304   // 4 n * 48 ytiles * 12 xtiles

// ---------------- scratch (device globals; no allocation) ----------------
__device__ float g_hs[BB*8*HW];
__device__ float g_cs[BB*8*HW];
__device__ float g_fic[BB*24*HW];      // raw f,i,c gate conv outputs
__device__ float g_r[BB*NFH*HW];       // [cs(8), sigmoid(q)(32)]
__device__ float g_y0[BB*NFH*HW];      // conv0 raw output (pre-BN)
__device__ float g_y1[BB*NFH*HW];      // conv1 raw output (pre-BN)
__device__ __align__(16) unsigned int g_wg [5*9*56*8];   // gates tf32 weights (frag layout)
__device__ __align__(16) unsigned int g_wc0[5*25*40*8];  // conv5 W0 tf32
__device__ __align__(16) unsigned int g_wc1[5*25*40*8];  // conv5 W1 tf32
__device__ float g_bgate[56];
__device__ float g_wtailT[NFH*25*12];  // [ci][tap][co(12, pad)] transposed tail weights
__device__ float g_btail[11];
__device__ float g_partS[NFH*NPART];
__device__ float g_partQ[NFH*NPART];
__device__ float g_bna[2][NFH];        // BN fused scale
__device__ float g_bnb[2][NFH];        // BN fused shift

// ---------------- helpers ----------------
__device__ __forceinline__ float sigm(float x) { return 1.f / (1.f + expf(-x)); }

__device__ __forceinline__ unsigned int to_tf32(float x) {
    unsigned int t;
    asm("cvt.rna.tf32.f32 %0, %1;" : "=r"(t) : "f"(x));
    return t;
}
__device__ __forceinline__ void mma_tf32(float c[4],
        unsigned int a0, unsigned int a1, unsigned int a2, unsigned int a3,
        unsigned int b0, unsigned int b1) {
    asm volatile("mma.sync.aligned.m16n8k8.row.col.f32.tf32.tf32.f32 "
        "{%0,%1,%2,%3}, {%4,%5,%6,%7}, {%8,%9}, {%0,%1,%2,%3};"
        : "+f"(c[0]), "+f"(c[1]), "+f"(c[2]), "+f"(c[3])
        : "r"(a0), "r"(a1), "r"(a2), "r"(a3), "r"(b0), "r"(b1));
}

// f32x2 helpers (tail kernel only)
__device__ __forceinline__ unsigned long long pack2(float x) {
    unsigned long long r;
    asm("mov.b64 %0, {%1, %1};" : "=l"(r) : "r"(__float_as_uint(x)));
    return r;
}
__device__ __forceinline__ void fma2(unsigned long long& a, unsigned long long x, unsigned long long w) {
    asm("fma.rn.f32x2 %0, %1, %2, %0;" : "+l"(a) : "l"(x), "l"(w));
}
__device__ __forceinline__ float2 unpack2(unsigned long long v) {
    unsigned int lo, hi;
    asm("mov.b64 {%0, %1}, %2;" : "=r"(lo), "=r"(hi) : "l"(v));
    return make_float2(__uint_as_float(lo), __uint_as_float(hi));
}

// ---------------- init / prep ----------------
__global__ void zero_state() {
    int i = blockIdx.x * blockDim.x + threadIdx.x;
    if (i < BB*8*HW) { g_hs[i] = 0.f; g_cs[i] = 0.f; }
}

// gates weights to tf32 fragment-interleaved layout:
// g_wg[ks][tap][n][e], e = (k%4)*2 + k/4, value = W[n][ci=ks*8+k][tap]
__global__ void prep_gatew(const float* __restrict__ Wf, const float* __restrict__ bf,
                           const float* __restrict__ Wi, const float* __restrict__ bi,
                           const float* __restrict__ Wc, const float* __restrict__ bc,
                           const float* __restrict__ Wq, const float* __restrict__ bq) {
    int i = blockIdx.x * 256 + threadIdx.x;
    if (i < 5*9*56*8) {
        int ks = i / 4032, r = i % 4032;
        int tap = r / 448, r2 = r % 448;
        int nco = r2 / 8, e = r2 % 8;
        int k = (e >> 1) + 4 * (e & 1);
        int ci = ks * 8 + k;
        const float* W; int o;
        if (nco < 8)       { W = Wf; o = nco; }
        else if (nco < 16) { W = Wi; o = nco - 8; }
        else if (nco < 24) { W = Wc; o = nco - 16; }
        else               { W = Wq; o = nco - 24; }
        g_wg[i] = to_tf32(W[(o * NFH + ci) * 9 + tap]);
    }
    if (i < 56)
        g_bgate[i] = (i < 8) ? bf[i] : (i < 16) ? bi[i-8] : (i < 24) ? bc[i-16] : bq[i-24];
}

// conv5 weights: g_wcX[ks][tap][n][e]
__global__ void prep_conv5w(const float* __restrict__ W, int which) {
    int i = blockIdx.x * 256 + threadIdx.x;
    if (i >= 5*25*40*8) return;
    int ks = i / 8000, r = i % 8000;
    int tap = r / 320, r2 = r % 320;
    int nco = r2 / 8, e = r2 % 8;
    int k = (e >> 1) + 4 * (e & 1);
    int ci = ks * 8 + k;
    unsigned int tv = to_tf32(W[(nco * NFH + ci) * 25 + tap]);
    if (which) g_wc1[i] = tv; else g_wc0[i] = tv;
}

__global__ void prep_tail(const float* __restrict__ W2, const float* __restrict__ b2w,
                          const float* __restrict__ Wh, const float* __restrict__ bh) {
    int i = blockIdx.x * blockDim.x + threadIdx.x;
    if (i < NFH * 25 * 12) {
        int o = i % 12;
        int rt = i / 12;            // ci*25 + tap
        int ci = rt / 25, k = rt % 25, ky = k / 5, kx = k % 5;
        float v = 0.f;
        if (o < 3) {
            v = W2[(o * NFH + ci) * 25 + k];
        } else if (o < 11) {
            int oo = o - 3;
            if (ky >= 1 && ky <= 3 && kx >= 1 && kx <= 3)
                v = Wh[(oo * NFH + ci) * 9 + (ky - 1) * 3 + (kx - 1)];
        }
        g_wtailT[i] = v;
    }
    if (i < 11) g_btail[i] = (i < 3) ? b2w[i] : bh[i - 3];
}

// ---------------- gates: 3x3 conv 40->56 via tf32 mma ----------------
// block = 4 warps; tile = 16 wide x 4 rows (1 row per warp, m = x within row)
__global__ __launch_bounds__(128) void gates_mma(const float* __restrict__ xin, int t) {
    __shared__ unsigned int sA[8][8][21];               // [ci_local][row][col] tf32
    __shared__ __align__(16) unsigned int sB[9*56*8];   // 4032 words
    int n = blockIdx.z;
    int x0 = blockIdx.x * 16, y0 = blockIdx.y * 4;
    int tid = threadIdx.x, lane = tid & 31, wid = tid >> 5;
    int kci = lane & 3, px = lane >> 2;
    float c[7][4];
    #pragma unroll
    for (int j = 0; j < 7; j++) { c[j][0]=c[j][1]=c[j][2]=c[j][3]=0.f; }

    #pragma unroll 1
    for (int ks = 0; ks < 5; ks++) {
        __syncthreads();
        {   // B slab: 4032 words = 1008 uint4
            const uint4* src = (const uint4*)(g_wg + ks * 4032);
            uint4* dst = (uint4*)sB;
            for (int i = tid; i < 1008; i += 128) dst[i] = src[i];
        }
        // A tile: 8 ci x 6 rows x 18 cols
        for (int i = tid; i < 8*6*18; i += 128) {
            int cl = i / 108, rr = (i / 18) % 6, cc = i % 18;
            int gy = y0 - 1 + rr, gx = x0 - 1 + cc;
            int ci = ks * 8 + cl;
            float v = 0.f;
            if (gy >= 0 && gy < HH && gx >= 0 && gx < WW) {
                const float* src = (ci < NF)
                    ? (xin + ((size_t)(n * DD + t) * NF + ci) * HW)
                    : (g_hs + ((size_t)n * 8 + (ci - NF)) * HW);
                v = src[gy * WW + gx];
            }
            sA[cl][rr][cc] = to_tf32(v);
        }
        __syncthreads();
        #pragma unroll
        for (int ky = 0; ky < 3; ky++) {
            int r = wid + ky;
            #pragma unroll
            for (int kx = 0; kx < 3; kx++) {
                unsigned int a0 = sA[kci  ][r][px + kx];
                unsigned int a1 = sA[kci  ][r][px + 8 + kx];
                unsigned int a2 = sA[kci+4][r][px + kx];
                unsigned int a3 = sA[kci+4][r][px + 8 + kx];
                const unsigned int* bb = &sB[(ky*3 + kx) * 448 + kci * 2];
                #pragma unroll
                for (int j = 0; j < 7; j++) {
                    uint2 b = *(const uint2*)(bb + (j * 8 + px) * 8);
                    mma_tf32(c[j], a0, a1, a2, a3, b.x, b.y);
                }
            }
        }
    }
    __syncthreads();
    // stage outputs (stride 68 avoids bank conflicts); 56*68 = 3808 <= 4032
    float* stage = (float*)sB;
    #pragma unroll
    for (int j = 0; j < 7; j++) {
        int co = j * 8 + 2 * kci;
        stage[ co      * 68 + wid * 16 + px    ] = c[j][0];
        stage[(co + 1) * 68 + wid * 16 + px    ] = c[j][1];
        stage[ co      * 68 + wid * 16 + px + 8] = c[j][2];
        stage[(co + 1) * 68 + wid * 16 + px + 8] = c[j][3];
    }
    __syncthreads();
    for (int i = tid; i < 56 * 64; i += 128) {
        int co = i >> 6, m = i & 63;
        int rr = m >> 4, cc = m & 15;
        float v = stage[co * 68 + rr * 16 + cc] + g_bgate[co];
        size_t off = (size_t)(y0 + rr) * WW + x0 + cc;
        if (co < 24) g_fic[((size_t)n * 24 + co) * HW + off] = v;
        else         g_r[((size_t)n * NFH + 8 + (co - 24)) * HW + off] = 1.f / (1.f + expf(-v));
    }
}

// ---------------- LSTM cell state update ----------------
__global__ void cs_update() {
    int i = blockIdx.x * 256 + threadIdx.x;
    if (i >= BB * 8 * HW) return;
    int n = i / (8 * HW);
    int r = i % (8 * HW);
    int c = r / HW, p = r % HW;
    size_t base = (size_t)n * 24 * HW + p;
    float zf = g_fic[base + (size_t)c * HW];
    float zi = g_fic[base + (size_t)(8 + c) * HW];
    float zc = g_fic[base + (size_t)(16 + c) * HW];
    float cs = sigm(zf) * g_cs[i] + sigm(zi) * tanhf(zc);
    g_cs[i] = cs;
    g_r[((size_t)n * NFH + c) * HW + p] = cs;
}

// ---------------- 5x5 conv 40->40 via tf32 mma, with BN partials ----------------
template <int PHASE>
__global__ __launch_bounds__(128) void conv5_mma() {
    __shared__ unsigned int sA[8][8][21];                 // [ci_local][row][col]
    __shared__ __align__(16) unsigned int sB[25*40*8];    // 8000 words (32KB)
    __shared__ float red[4][4][5][4];
    const unsigned int* Wt = PHASE ? g_wc1 : g_wc0;
    int n = blockIdx.z;
    int x0 = blockIdx.x * 16, y0 = blockIdx.y * 4;
    int tid = threadIdx.x, lane = tid & 31, wid = tid >> 5;
    int kci = lane & 3, px = lane >> 2;
    float c[5][4];
    #pragma unroll
    for (int j = 0; j < 5; j++) { c[j][0]=c[j][1]=c[j][2]=c[j][3]=0.f; }

    #pragma unroll 1
    for (int ks = 0; ks < 5; ks++) {
        __syncthreads();
        {   // B slab: 8000 words = 2000 uint4
            const uint4* src = (const uint4*)(Wt + ks * 8000);
            uint4* dst = (uint4*)sB;
            for (int i = tid; i < 2000; i += 128) dst[i] = src[i];
        }
        // A tile: 8 ci x 8 rows x 20 cols, with fused BN+relu for PHASE 1
        for (int i = tid; i < 8*8*20; i += 128) {
            int cl = i / 160, rr = (i / 20) % 8, cc = i % 20;
            int gy = y0 - 2 + rr, gx = x0 - 2 + cc;
            int ci = ks * 8 + cl;
            float v = 0.f;
            if (gy >= 0 && gy < HH && gx >= 0 && gx < WW) {
                const float* src = (PHASE ? g_y0 : g_r) + ((size_t)n * NFH + ci) * HW;
                v = src[gy * WW + gx];
                if (PHASE) v = fmaxf(0.f, fmaf(v, g_bna[0][ci], g_bnb[0][ci]));
            }
            sA[cl][rr][cc] = to_tf32(v);
        }
        __syncthreads();
        #pragma unroll
        for (int ky = 0; ky < 5; ky++) {
            int r = wid + ky;
            #pragma unroll
            for (int kx = 0; kx < 5; kx++) {
                unsigned int a0 = sA[kci  ][r][px + kx];
                unsigned int a1 = sA[kci  ][r][px + 8 + kx];
                unsigned int a2 = sA[kci+4][r][px + kx];
                unsigned int a3 = sA[kci+4][r][px + 8 + kx];
                const unsigned int* bb = &sB[(ky*5 + kx) * 320 + kci * 2];
                #pragma unroll
                for (int j = 0; j < 5; j++) {
                    uint2 b = *(const uint2*)(bb + (j * 8 + px) * 8);
                    mma_tf32(c[j], a0, a1, a2, a3, b.x, b.y);
                }
            }
        }
    }
    __syncthreads();
    // stage outputs; 40*68 = 2720 <= 8000
    float* stage = (float*)sB;
    #pragma unroll
    for (int j = 0; j < 5; j++) {
        int co = j * 8 + 2 * kci;
        stage[ co      * 68 + wid * 16 + px    ] = c[j][0];
        stage[(co + 1) * 68 + wid * 16 + px    ] = c[j][1];
        stage[ co      * 68 + wid * 16 + px + 8] = c[j][2];
        stage[(co + 1) * 68 + wid * 16 + px + 8] = c[j][3];
    }
    // BN partial shuffle reduce (per warp, then cross-warp via red[])
    #pragma unroll
    for (int j = 0; j < 5; j++) {
        float se = c[j][0] + c[j][2];
        float so = c[j][1] + c[j][3];
        float qe = c[j][0]*c[j][0] + c[j][2]*c[j][2];
        float qo = c[j][1]*c[j][1] + c[j][3]*c[j][3];
        #pragma unroll
        for (int off = 16; off >= 4; off >>= 1) {
            se += __shfl_down_sync(0xffffffffu, se, off);
            so += __shfl_down_sync(0xffffffffu, so, off);
            qe += __shfl_down_sync(0xffffffffu, qe, off);
            qo += __shfl_down_sync(0xffffffffu, qo, off);
        }
        if (lane < 4) {
            red[wid][lane][j][0] = se; red[wid][lane][j][1] = so;
            red[wid][lane][j][2] = qe; red[wid][lane][j][3] = qo;
        }
    }
    __syncthreads();
    float* outp = PHASE ? g_y1 : g_y0;
    for (int i = tid; i < 40 * 64; i += 128) {
        int co = i >> 6, m = i & 63;
        int rr = m >> 4, cc = m & 15;
        outp[((size_t)n * NFH + co) * HW + (size_t)(y0 + rr) * WW + x0 + cc]
            = stage[co * 68 + rr * 16 + cc];
    }
    if (tid < 40) {
        int co = tid, j = co >> 3, kk = (co & 7) >> 1, par = co & 1;
        float S = red[0][kk][j][par]   + red[1][kk][j][par]
                + red[2][kk][j][par]   + red[3][kk][j][par];
        float Q = red[0][kk][j][2+par] + red[1][kk][j][2+par]
                + red[2][kk][j][2+par] + red[3][kk][j][2+par];
        int bid = (n * 48 + blockIdx.y) * 12 + blockIdx.x;
        g_partS[co * NPART + bid] = S;
        g_partQ[co * NPART + bid] = Q;
    }
}

// ---------------- BN statistics finalize ----------------
__global__ void bn_reduce(int phase, const float* __restrict__ gamma, const float* __restrict__ beta) {
    int ch = blockIdx.x;
    int tid = threadIdx.x;
    __shared__ float ss[128], sq[128];
    float s = 0.f, q = 0.f;
    for (int i = tid; i < NPART; i += 128) { s += g_partS[ch * NPART + i]; q += g_partQ[ch * NPART + i]; }
    ss[tid] = s; sq[tid] = q;
    __syncthreads();
    for (int off = 64; off; off >>= 1) {
        if (tid < off) { ss[tid] += ss[tid + off]; sq[tid] += sq[tid + off]; }
        __syncthreads();
    }
    if (tid == 0) {
        const float N = (float)(BB * HW);
        float mean = ss[0] / N;
        float var = sq[0] / N - mean * mean;
        float inv = rsqrtf(var + EPS);
        float a = gamma[ch] * inv;
        g_bna[phase][ch] = a;
        g_bnb[phase][ch] = beta[ch] - mean * a;
    }
}

// ---------------- tail: combined 5x5 conv, 40 -> 12(pad), f32x2, 32x16 tile ------------
__global__ __launch_bounds__(128, 4) void tail_kernel(float* __restrict__ outp, int t) {
    __shared__ float st[2][20][40];   // 36 cols used
    int n = blockIdx.z;
    int tx = threadIdx.x, ty = threadIdx.y;
    int tid = ty * 8 + tx;
    unsigned long long acc[4][6];
    #pragma unroll
    for (int p = 0; p < 4; p++)
        #pragma unroll
        for (int j = 0; j < 6; j++) acc[p][j] = 0ull;
    int y0 = blockIdx.y * 16, x0 = blockIdx.x * 32;

    auto loadci = [&](int ci, int buf) {
        const float* src = g_y1 + ((size_t)n * NFH + ci) * HW;
        float a = g_bna[1][ci], b = g_bnb[1][ci];
        for (int i = tid; i < 20 * 36; i += 128) {
            int r = i / 36, c = i % 36;
            int yy = y0 - 2 + r, xx = x0 - 2 + c;
            float v = 0.f;
            if (yy >= 0 && yy < HH && xx >= 0 && xx < WW)
                v = fmaxf(0.f, fmaf(src[yy * WW + xx], a, b));
            st[buf][r][c] = v;
        }
    };

    loadci(0, 0);
    __syncthreads();
    for (int ci = 0; ci < NFH; ci++) {
        if (ci + 1 < NFH) loadci(ci + 1, (ci + 1) & 1);
        int buf = ci & 1;
        #pragma unroll
        for (int ky = 0; ky < 5; ky++) {
            const float* row = &st[buf][ty + ky][tx * 4];
            float4 t0 = *(const float4*)row;
            float4 t1 = *(const float4*)(row + 4);
            unsigned long long xx[8];
            xx[0]=pack2(t0.x); xx[1]=pack2(t0.y); xx[2]=pack2(t0.z); xx[3]=pack2(t0.w);
            xx[4]=pack2(t1.x); xx[5]=pack2(t1.y); xx[6]=pack2(t1.z); xx[7]=pack2(t1.w);
            #pragma unroll
            for (int kx = 0; kx < 5; kx++) {
                const ulonglong2* wp =
                    (const ulonglong2*)&g_wtailT[(ci * 25 + ky * 5 + kx) * 12];
                ulonglong2 wA = __ldg(wp), wB = __ldg(wp + 1), wC = __ldg(wp + 2);
                #pragma unroll
                for (int p = 0; p < 4; p++) {
                    unsigned long long xv = xx[p + kx];
                    fma2(acc[p][0], xv, wA.x);
                    fma2(acc[p][1], xv, wA.y);
                    fma2(acc[p][2], xv, wB.x);
                    fma2(acc[p][3], xv, wB.y);
                    fma2(acc[p][4], xv, wC.x);
                    fma2(acc[p][5], xv, wC.y);
                }
            }
        }
        __syncthreads();
    }
    float v[4][12];
    #pragma unroll
    for (int p = 0; p < 4; p++) {
        #pragma unroll
        for (int j = 0; j < 6; j++) {
            float2 u = unpack2(acc[p][j]);
            v[p][2*j] = u.x; v[p][2*j+1] = u.y;
        }
    }
    int yy = y0 + ty, xb = x0 + tx * 4;
    #pragma unroll
    for (int co = 0; co < 11; co++) {
        float b = g_btail[co];
        float4 o; o.x=v[0][co]+b; o.y=v[1][co]+b; o.z=v[2][co]+b; o.w=v[3][co]+b;
        if (co < 3) {
            *(float4*)&outp[(((size_t)n * 3 + co) * DD + t) * HW + yy * WW + xb] = o;
        } else {
            *(float4*)&g_hs[((size_t)n * 8 + (co - 3)) * HW + yy * WW + xb] = o;
        }
    }
}

// ---------------- launcher ----------------
extern "C" void kernel_launch(void* const* d_in, const int* in_sizes, int n_in,
                              void* d_out, int out_size) {
    const float* x1  = (const float*)d_in[0];
    const float* x2  = (const float*)d_in[1];
    const float* Wf  = (const float*)d_in[2];
    const float* bf  = (const float*)d_in[3];
    const float* Wi  = (const float*)d_in[4];
    const float* bi  = (const float*)d_in[5];
    const float* Wc  = (const float*)d_in[6];
    const float* bc  = (const float*)d_in[7];
    const float* Wq  = (const float*)d_in[8];
    const float* bq  = (const float*)d_in[9];
    const float* W0  = (const float*)d_in[10];
    const float* g0  = (const float*)d_in[11];
    const float* be0 = (const float*)d_in[12];
    const float* W1  = (const float*)d_in[13];
    const float* g1  = (const float*)d_in[14];
    const float* be1 = (const float*)d_in[15];
    const float* W2  = (const float*)d_in[16];
    const float* b2w = (const float*)d_in[17];
    const float* Wh  = (const float*)d_in[18];
    const float* bh  = (const float*)d_in[19];
    float* out = (float*)d_out;

    dim3 gM(12, 48, BB);       // mma conv tiles: 16x4 px
    dim3 cb(8, 16, 1);
    dim3 gTail(6, 12, BB);

    zero_state<<<(BB*8*HW + 255) / 256, 256>>>();
    prep_gatew<<<(5*9*56*8 + 255) / 256, 256>>>(Wf, bf, Wi, bi, Wc, bc, Wq, bq);
    prep_conv5w<<<(5*25*40*8 + 255) / 256, 256>>>(W0, 0);
    prep_conv5w<<<(5*25*40*8 + 255) / 256, 256>>>(W1, 1);
    prep_tail<<<(NFH*25*12 + 255) / 256, 256>>>(W2, b2w, Wh, bh);

    const size_t OUT_HALF = (size_t)BB * 3 * DD * HW;
    for (int t = 0; t < DD; t++) {
        for (int cell = 0; cell < 2; cell++) {
            gates_mma<<<gM, 128>>>(cell ? x2 : x1, t);
            cs_update<<<(BB*8*HW + 255) / 256, 256>>>();
            conv5_mma<0><<<gM, 128>>>();
            bn_reduce<<<NFH, 128>>>(0, g0, be0);
            conv5_mma<1><<<gM, 128>>>();
            bn_reduce<<<NFH, 128>>>(1, g1, be1);
            tail_kernel<<<gTail, cb>>>(out + (size_t)cell * OUT_HALF, t);
        }
    }
}